// round 1
// baseline (speedup 1.0000x reference)
#include <cuda_runtime.h>
#include <cuda_bf16.h>

#define HH 1024
#define WW 1024
#define NQROW (WW / 4)   // float4 quads per row = 256

static constexpr int NBLOCKS  = 1184;  // 148 SMs * 8
static constexpr int NTHREADS = 256;

__device__ float g_part[NBLOCKS];

__global__ __launch_bounds__(NTHREADS)
void lap_main_kernel(const float* __restrict__ f, int total_q) {
    float acc = 0.0f;
    const int stride = gridDim.x * blockDim.x;
    for (int t = blockIdx.x * blockDim.x + threadIdx.x; t < total_q; t += stride) {
        const int rq = t >> 8;            // global row index (plane*H + i)
        const int jq = t & (NQROW - 1);   // quad index within row
        const int i  = rq & (HH - 1);     // row within plane
        const float* __restrict__ base = f + ((size_t)(rq >> 10) << 20); // plane base
        const float* __restrict__ cur  = base + ((size_t)i << 10);
        const int j0 = jq << 2;

        if (i > 0 && i < HH - 1 && jq > 0 && jq < NQROW - 1) {
            // ---- fast interior path: no clamping needed ----
            const float* __restrict__ prv = cur - WW;
            const float* __restrict__ nxt = cur + WW;
            const float4 a = *(const float4*)(prv + j0);
            const float4 c = *(const float4*)(cur + j0);
            const float4 b = *(const float4*)(nxt + j0);
            const float al = prv[j0 - 1], ar = prv[j0 + 4];
            const float cl = cur[j0 - 1], cr = cur[j0 + 4];
            const float bl = nxt[j0 - 1], br = nxt[j0 + 4];

            float v, d;
            // pixel j0
            v = c.x;
            d = v - al;  acc += d * d;  d = v - a.x; acc += d * d;  d = v - a.y; acc += d * d;
            d = v - cl;  acc += d * d;  d = v - c.y; acc += d * d;
            d = v - bl;  acc += d * d;  d = v - b.x; acc += d * d;  d = v - b.y; acc += d * d;
            // pixel j0+1
            v = c.y;
            d = v - a.x; acc += d * d;  d = v - a.y; acc += d * d;  d = v - a.z; acc += d * d;
            d = v - c.x; acc += d * d;  d = v - c.z; acc += d * d;
            d = v - b.x; acc += d * d;  d = v - b.y; acc += d * d;  d = v - b.z; acc += d * d;
            // pixel j0+2
            v = c.z;
            d = v - a.y; acc += d * d;  d = v - a.z; acc += d * d;  d = v - a.w; acc += d * d;
            d = v - c.y; acc += d * d;  d = v - c.w; acc += d * d;
            d = v - b.y; acc += d * d;  d = v - b.z; acc += d * d;  d = v - b.w; acc += d * d;
            // pixel j0+3
            v = c.w;
            d = v - a.z; acc += d * d;  d = v - a.w; acc += d * d;  d = v - ar;  acc += d * d;
            d = v - c.z; acc += d * d;  d = v - cr;  acc += d * d;
            d = v - b.z; acc += d * d;  d = v - b.w; acc += d * d;  d = v - br;  acc += d * d;
        } else {
            // ---- boundary path: exact clamped-neighbor semantics ----
            #pragma unroll
            for (int k = 0; k < 4; k++) {
                const int j = j0 + k;
                const float v = cur[j];
                #pragma unroll
                for (int di = -1; di <= 1; di++) {
                    int ii = i + di;
                    ii = ii < 0 ? 0 : (ii > HH - 1 ? HH - 1 : ii);
                    const float* __restrict__ r = base + ((size_t)ii << 10);
                    #pragma unroll
                    for (int dj = -1; dj <= 1; dj++) {
                        if (di == 0 && dj == 0) continue;
                        int jj = j + dj;
                        jj = jj < 0 ? 0 : (jj > WW - 1 ? WW - 1 : jj);
                        const float d = v - r[jj];
                        acc += d * d;
                    }
                }
            }
        }
    }

    // ---- deterministic block reduction ----
    __shared__ float s[NTHREADS / 32];
    #pragma unroll
    for (int o = 16; o > 0; o >>= 1)
        acc += __shfl_down_sync(0xffffffffu, acc, o);
    if ((threadIdx.x & 31) == 0) s[threadIdx.x >> 5] = acc;
    __syncthreads();
    if (threadIdx.x < NTHREADS / 32) {
        float v = s[threadIdx.x];
        #pragma unroll
        for (int o = NTHREADS / 64; o > 0; o >>= 1)
            v += __shfl_down_sync(0xffu, v, o);
        if (threadIdx.x == 0) g_part[blockIdx.x] = v;
    }
}

__global__ __launch_bounds__(256)
void lap_reduce_kernel(float* __restrict__ out, int nparts) {
    __shared__ double s[256];
    double v = 0.0;
    for (int i = threadIdx.x; i < nparts; i += 256) v += (double)g_part[i];
    s[threadIdx.x] = v;
    __syncthreads();
    #pragma unroll
    for (int o = 128; o > 0; o >>= 1) {
        if (threadIdx.x < o) s[threadIdx.x] += s[threadIdx.x + o];
        __syncthreads();
    }
    if (threadIdx.x == 0) out[0] = (float)s[0];
}

extern "C" void kernel_launch(void* const* d_in, const int* in_sizes, int n_in,
                              void* d_out, int out_size) {
    const float* f = (const float*)d_in[0];
    const int n = in_sizes[0];        // 4*12*1024*1024 = 50331648
    const int total_q = n >> 2;       // float4 quads
    lap_main_kernel<<<NBLOCKS, NTHREADS>>>(f, total_q);
    lap_reduce_kernel<<<1, 256>>>((float*)d_out, NBLOCKS);
}

// round 2
// speedup vs baseline: 1.4572x; 1.4572x over previous
#include <cuda_runtime.h>
#include <cuda_bf16.h>

#define HH 1024
#define WW 1024
#define NQROW (WW / 4)   // float4 quads per row = 256

static constexpr int NBLOCKS  = 1184;
static constexpr int NTHREADS = 256;

__device__ float        g_part[NBLOCKS];
__device__ unsigned int g_count = 0;

typedef unsigned long long ull;

__device__ __forceinline__ ull pk(float lo, float hi) {
    ull r; asm("mov.b64 %0, {%1, %2};" : "=l"(r) : "f"(lo), "f"(hi)); return r;
}
__device__ __forceinline__ ull sub2(ull a, ull b) {
    ull r; asm("sub.rn.f32x2 %0, %1, %2;" : "=l"(r) : "l"(a), "l"(b)); return r;
}
__device__ __forceinline__ ull fma2(ull a, ull b, ull c) {
    ull r; asm("fma.rn.f32x2 %0, %1, %2, %3;" : "=l"(r) : "l"(a), "l"(b), "l"(c)); return r;
}
__device__ __forceinline__ void unpk(ull v, float& lo, float& hi) {
    asm("mov.b64 {%0, %1}, %2;" : "=f"(lo), "=f"(hi) : "l"(v));
}

// total = 2 * ( S_directed + S_edge )
//   S_directed: offsets (0,1),(1,-1),(1,0),(1,1), in-range targets only
//   S_edge:     horizontal pairs in rows 0 and H-1, vertical pairs in cols 0 and W-1
__global__ __launch_bounds__(NTHREADS)
void lap_kernel(const float* __restrict__ f, float* __restrict__ out, int total_q) {
    ull   acc2 = 0;      // packed f32x2 accumulator (fast path)
    float accs = 0.0f;   // scalar accumulator (boundary path)
    const int stride = gridDim.x * blockDim.x;

    for (int t = blockIdx.x * blockDim.x + threadIdx.x; t < total_q; t += stride) {
        const int rq = t >> 8;            // global row (plane*H + i)
        const int jq = t & (NQROW - 1);   // quad within row
        const int i  = rq & (HH - 1);     // row within plane
        const float* __restrict__ base = f + ((size_t)(rq >> 10) << 20);
        const float* __restrict__ cur  = base + ((size_t)i << 10);
        const int j0 = jq << 2;

        if (i >= 1 && i <= HH - 2 && jq >= 1 && jq <= NQROW - 2) {
            // ---- fast path: all directed targets in-range, no edge duplicates ----
            const float* __restrict__ nxt = cur + WW;
            const float4 c = *(const float4*)(cur + j0);
            const float4 b = *(const float4*)(nxt + j0);
            const float cr = cur[j0 + 4];
            const float bl = nxt[j0 - 1], br = nxt[j0 + 4];

            const ull vp01 = pk(c.x, c.y), vp23 = pk(c.z, c.w);
            ull d;
            // right: (c.y,c.z) , (c.w,cr)
            d = sub2(vp01, pk(c.y, c.z)); acc2 = fma2(d, d, acc2);
            d = sub2(vp23, pk(c.w, cr));  acc2 = fma2(d, d, acc2);
            // down: (b.x,b.y) , (b.z,b.w)
            d = sub2(vp01, pk(b.x, b.y)); acc2 = fma2(d, d, acc2);
            d = sub2(vp23, pk(b.z, b.w)); acc2 = fma2(d, d, acc2);
            // down-left: (bl,b.x) , (b.y,b.z)
            const ull m12 = pk(b.y, b.z);
            d = sub2(vp01, pk(bl, b.x));  acc2 = fma2(d, d, acc2);
            d = sub2(vp23, m12);          acc2 = fma2(d, d, acc2);
            // down-right: (b.y,b.z) , (b.w,br)
            d = sub2(vp01, m12);          acc2 = fma2(d, d, acc2);
            d = sub2(vp23, pk(b.w, br));  acc2 = fma2(d, d, acc2);
        } else {
            // ---- boundary path: directed + edge-line duplicates, predicated ----
            const bool hasD  = (i + 1 <= HH - 1);
            const bool hRow  = (i == 0) || (i == HH - 1);   // top/bottom row
            const float* __restrict__ nxt = cur + WW;       // only deref if hasD
            #pragma unroll
            for (int k = 0; k < 4; k++) {
                const int j = j0 + k;
                const float v = cur[j];
                const bool hasR = (j + 1 <= WW - 1);
                if (hasR) {
                    const float d = v - cur[j + 1];
                    const float q = d * d;
                    accs += hRow ? (q + q) : q;
                }
                if (hasD) {
                    const bool vCol = (j == 0) || (j == WW - 1);
                    float d = v - nxt[j];
                    float q = d * d;
                    accs += vCol ? (q + q) : q;
                    if (j > 0)  { d = v - nxt[j - 1]; accs += d * d; }
                    if (hasR)   { d = v - nxt[j + 1]; accs += d * d; }
                }
            }
        }
    }

    // ---- fold packed lanes into scalar ----
    float lo, hi; unpk(acc2, lo, hi);
    float acc = accs + lo + hi;

    // ---- deterministic block reduction ----
    __shared__ float swarp[NTHREADS / 32];
    #pragma unroll
    for (int o = 16; o > 0; o >>= 1)
        acc += __shfl_down_sync(0xffffffffu, acc, o);
    if ((threadIdx.x & 31) == 0) swarp[threadIdx.x >> 5] = acc;
    __syncthreads();
    if (threadIdx.x < NTHREADS / 32) {
        float v = swarp[threadIdx.x];
        #pragma unroll
        for (int o = NTHREADS / 64; o > 0; o >>= 1)
            v += __shfl_down_sync(0xffu, v, o);
        if (threadIdx.x == 0) g_part[blockIdx.x] = v;
    }

    // ---- last-block final reduction (no second launch) ----
    __shared__ bool isLast;
    if (threadIdx.x == 0) {
        __threadfence();
        isLast = (atomicAdd(&g_count, 1u) == (unsigned)gridDim.x - 1u);
    }
    __syncthreads();
    if (isLast) {
        volatile float* gp = g_part;
        double v = 0.0;
        for (int idx = threadIdx.x; idx < NBLOCKS; idx += NTHREADS) v += (double)gp[idx];
        __shared__ double sd[NTHREADS];
        sd[threadIdx.x] = v;
        __syncthreads();
        #pragma unroll
        for (int o = NTHREADS / 2; o > 0; o >>= 1) {
            if (threadIdx.x < o) sd[threadIdx.x] += sd[threadIdx.x + o];
            __syncthreads();
        }
        if (threadIdx.x == 0) {
            out[0] = (float)(2.0 * sd[0]);
            g_count = 0;   // reset for next graph replay
        }
    }
}

extern "C" void kernel_launch(void* const* d_in, const int* in_sizes, int n_in,
                              void* d_out, int out_size) {
    const float* f = (const float*)d_in[0];
    const int n = in_sizes[0];
    const int total_q = n >> 2;
    lap_kernel<<<NBLOCKS, NTHREADS>>>(f, (float*)d_out, total_q);
}